// round 7
// baseline (speedup 1.0000x reference)
#include <cuda_runtime.h>
#include <cstdint>

#define NN 100000
#define EE 800000
#define IN_DIM 256
#define H 4
#define D 32
#define HD 128
#define SLOPE 0.2f

// ---------------- scratch (no allocations allowed) ----------------
__device__ float g_feat[NN * HD];     // projected features of current layer
__device__ float g_h1[NN * HD];       // layer-0 output (residual for layer 1)
__device__ float g_el[NN * H];
__device__ float g_er[NN * H];
__device__ float g_w[EE * H];         // exp(score) in CSR order
__device__ int   g_deg[NN];           // zero at load; re-zeroed by scan3
__device__ int   g_rowptr[NN + 1];
__device__ int   g_cursor[NN];
__device__ int   g_partial[256];
__device__ int   g_csr_src[EE];
__device__ int   g_csr_dst[EE];
__device__ int   g_csr_eid[EE];

__device__ __forceinline__ float elu1(float x) {
    return x > 0.f ? x : expm1f(x);
}
__device__ __forceinline__ float tf32r(float x) {
    uint32_t u;
    asm("cvt.rna.tf32.f32 %0, %1;" : "=r"(u) : "f"(x));
    return __uint_as_float(u);
}
__device__ __forceinline__ float4 tf32r4(float4 v) {
    return make_float4(tf32r(v.x), tf32r(v.y), tf32r(v.z), tf32r(v.w));
}
__device__ __forceinline__ float lrelu(float x) {
    return x > 0.f ? x : SLOPE * x;
}

// ================= CSR build =================
__global__ void count_deg_kernel(const int* __restrict__ ei) {
    int e = blockIdx.x * blockDim.x + threadIdx.x;
    if (e < EE) atomicAdd(&g_deg[ei[EE + e]], 1);
}

#define SCAN_BS 512
#define NBLK1 ((NN + SCAN_BS - 1) / SCAN_BS)   // 196

__global__ __launch_bounds__(SCAN_BS) void scan1_kernel() {
    __shared__ int s[SCAN_BS];
    int t = threadIdx.x;
    int i = blockIdx.x * SCAN_BS + t;
    int v = (i < NN) ? g_deg[i] : 0;
    s[t] = v;
    __syncthreads();
#pragma unroll
    for (int off = 1; off < SCAN_BS; off <<= 1) {
        int x = (t >= off) ? s[t - off] : 0;
        __syncthreads();
        s[t] += x;
        __syncthreads();
    }
    if (i < NN) g_rowptr[i] = s[t] - v;      // exclusive within block
    if (t == SCAN_BS - 1) g_partial[blockIdx.x] = s[t];
}

__global__ __launch_bounds__(256) void scan2_kernel() {
    __shared__ int s[256];
    int t = threadIdx.x;
    int v = (t < NBLK1) ? g_partial[t] : 0;
    s[t] = v;
    __syncthreads();
#pragma unroll
    for (int off = 1; off < 256; off <<= 1) {
        int x = (t >= off) ? s[t - off] : 0;
        __syncthreads();
        s[t] += x;
        __syncthreads();
    }
    if (t < NBLK1) g_partial[t] = s[t] - v;  // exclusive across blocks
}

__global__ __launch_bounds__(SCAN_BS) void scan3_kernel() {
    int t = threadIdx.x;
    int i = blockIdx.x * SCAN_BS + t;
    if (i < NN) {
        int r = g_rowptr[i] + g_partial[blockIdx.x];
        g_rowptr[i] = r;
        g_cursor[i] = r;
        g_deg[i] = 0;                        // re-zero for next replay
    }
    if (i == 0) g_rowptr[NN] = EE;
}

__global__ void fill_csr_kernel(const int* __restrict__ ei) {
    int e = blockIdx.x * blockDim.x + threadIdx.x;
    if (e >= EE) return;
    int s = ei[e], d = ei[EE + e];
    int pos = atomicAdd(&g_cursor[d], 1);
    g_csr_src[pos] = s;
    g_csr_dst[pos] = d;
    g_csr_eid[pos] = e;
}

// ========== TF32 tensor-core GEMM fused with attention dots ==========
// 64x128 block tile, 8 warps (2x4), warp tile 32x32, BK=16, double-buffered.
// 3 CTAs/SM for latency hiding; float4 smem fills (16B-aligned, bank-clean).
#define AS_S 20
#define BS_S 136

__global__ __launch_bounds__(256, 3) void sgemm_tf32(const float* __restrict__ A,
                                                     const float* __restrict__ B,
                                                     const float* __restrict__ al,
                                                     const float* __restrict__ ar,
                                                     float* __restrict__ C,
                                                     int M, int K) {
    __shared__ __align__(16) float As[2][64][AS_S];
    __shared__ __align__(16) float Bs[2][16][BS_S];
    int tid = threadIdx.x;
    int lane = tid & 31;
    int wid = tid >> 5;
    int warp_m = wid & 1;      // 2 m-warps * 32 rows
    int warp_n = wid >> 1;     // 4 n-warps * 32 cols (= head)
    int block_row = blockIdx.x * 64;

    float c[2][4][4];
#pragma unroll
    for (int i = 0; i < 2; i++)
#pragma unroll
        for (int j = 0; j < 4; j++)
#pragma unroll
            for (int k = 0; k < 4; k++) c[i][j][k] = 0.f;

    int ar_r = tid >> 2;           // 0..63 (A row)
    int ac = (tid & 3) * 4;        // 0,4,8,12
    int br = tid >> 5;             // 0..7
    int bc = (tid & 31) * 4;       // 0..124

    int gr = block_row + ar_r;
    bool av = gr < M;
    const float* Ap = A + (size_t)gr * K;

    int ntiles = K >> 4;
    float4 pa, pb0, pb1;
    {
        pa = av ? *(const float4*)(Ap + ac) : make_float4(0, 0, 0, 0);
        pb0 = *(const float4*)(B + (size_t)br * 128 + bc);
        pb1 = *(const float4*)(B + (size_t)(br + 8) * 128 + bc);
        *(float4*)&As[0][ar_r][ac] = tf32r4(pa);
        *(float4*)&Bs[0][br][bc] = tf32r4(pb0);
        *(float4*)&Bs[0][br + 8][bc] = tf32r4(pb1);
    }
    __syncthreads();

    int buf = 0;
    for (int kt = 0; kt < ntiles; kt++) {
        bool more = (kt + 1) < ntiles;
        if (more) {
            int kb = (kt + 1) * 16;
            pa = av ? *(const float4*)(Ap + kb + ac) : make_float4(0, 0, 0, 0);
            pb0 = *(const float4*)(B + (size_t)(kb + br) * 128 + bc);
            pb1 = *(const float4*)(B + (size_t)(kb + br + 8) * 128 + bc);
        }
#pragma unroll
        for (int ks = 0; ks < 2; ks++) {
            int k8 = ks * 8;
            uint32_t af[2][4];
            uint32_t bf[4][2];
#pragma unroll
            for (int mi = 0; mi < 2; mi++) {
                int r = warp_m * 32 + mi * 16 + (lane >> 2);
                int kc = k8 + (lane & 3);
                af[mi][0] = __float_as_uint(As[buf][r][kc]);
                af[mi][1] = __float_as_uint(As[buf][r + 8][kc]);
                af[mi][2] = __float_as_uint(As[buf][r][kc + 4]);
                af[mi][3] = __float_as_uint(As[buf][r + 8][kc + 4]);
            }
#pragma unroll
            for (int nj = 0; nj < 4; nj++) {
                int cc = warp_n * 32 + nj * 8 + (lane >> 2);
                int kr = k8 + (lane & 3);
                bf[nj][0] = __float_as_uint(Bs[buf][kr][cc]);
                bf[nj][1] = __float_as_uint(Bs[buf][kr + 4][cc]);
            }
#pragma unroll
            for (int mi = 0; mi < 2; mi++)
#pragma unroll
                for (int nj = 0; nj < 4; nj++) {
                    asm("mma.sync.aligned.m16n8k8.row.col.f32.tf32.tf32.f32 "
                        "{%0,%1,%2,%3}, {%4,%5,%6,%7}, {%8,%9}, {%0,%1,%2,%3};"
                        : "+f"(c[mi][nj][0]), "+f"(c[mi][nj][1]),
                          "+f"(c[mi][nj][2]), "+f"(c[mi][nj][3])
                        : "r"(af[mi][0]), "r"(af[mi][1]),
                          "r"(af[mi][2]), "r"(af[mi][3]),
                          "r"(bf[nj][0]), "r"(bf[nj][1]));
                }
        }
        if (more) {
            int nb = buf ^ 1;
            *(float4*)&As[nb][ar_r][ac] = tf32r4(pa);
            *(float4*)&Bs[nb][br][bc] = tf32r4(pb0);
            *(float4*)&Bs[nb][br + 8][bc] = tf32r4(pb1);
        }
        __syncthreads();
        buf ^= 1;
    }

    float alv[8], arv[8];
#pragma unroll
    for (int nj = 0; nj < 4; nj++) {
#pragma unroll
        for (int t = 0; t < 2; t++) {
            int col = warp_n * 32 + nj * 8 + (lane & 3) * 2 + t;
            alv[nj * 2 + t] = al[col];
            arv[nj * 2 + t] = ar[col];
        }
    }

#pragma unroll
    for (int mi = 0; mi < 2; mi++) {
        float sl0 = 0.f, sl1 = 0.f, sr0 = 0.f, sr1 = 0.f;
#pragma unroll
        for (int nj = 0; nj < 4; nj++) {
            int row0 = block_row + warp_m * 32 + mi * 16 + (lane >> 2);
            int col = warp_n * 32 + nj * 8 + (lane & 3) * 2;
            if (row0 < M)
                *(float2*)(C + (size_t)row0 * 128 + col) =
                    make_float2(c[mi][nj][0], c[mi][nj][1]);
            int row1 = row0 + 8;
            if (row1 < M)
                *(float2*)(C + (size_t)row1 * 128 + col) =
                    make_float2(c[mi][nj][2], c[mi][nj][3]);
            sl0 += c[mi][nj][0] * alv[nj * 2] + c[mi][nj][1] * alv[nj * 2 + 1];
            sl1 += c[mi][nj][2] * alv[nj * 2] + c[mi][nj][3] * alv[nj * 2 + 1];
            sr0 += c[mi][nj][0] * arv[nj * 2] + c[mi][nj][1] * arv[nj * 2 + 1];
            sr1 += c[mi][nj][2] * arv[nj * 2] + c[mi][nj][3] * arv[nj * 2 + 1];
        }
#pragma unroll
        for (int o = 1; o <= 2; o <<= 1) {
            sl0 += __shfl_xor_sync(0xffffffffu, sl0, o);
            sl1 += __shfl_xor_sync(0xffffffffu, sl1, o);
            sr0 += __shfl_xor_sync(0xffffffffu, sr0, o);
            sr1 += __shfl_xor_sync(0xffffffffu, sr1, o);
        }
        if ((lane & 3) == 0) {
            int row0 = block_row + warp_m * 32 + mi * 16 + (lane >> 2);
            int row1 = row0 + 8;
            if (row0 < M) {
                g_el[(size_t)row0 * 4 + warp_n] = sl0;
                g_er[(size_t)row0 * 4 + warp_n] = sr0;
            }
            if (row1 < M) {
                g_el[(size_t)row1 * 4 + warp_n] = sl1;
                g_er[(size_t)row1 * 4 + warp_n] = sr1;
            }
        }
    }
}

// ---------------- per-CSR-position: scores -> w = exp(z), + outputs ------
template <int LAYER>
__global__ void edge_w_kernel(float* __restrict__ atten,
                              float* __restrict__ e1) {
    int i = blockIdx.x * blockDim.x + threadIdx.x;
    if (i >= EE) return;
    int src = g_csr_src[i], dst = g_csr_dst[i], eid = g_csr_eid[i];
    float4 l = *(const float4*)(g_el + (size_t)src * 4);
    float4 r = *(const float4*)(g_er + (size_t)dst * 4);
    float z0 = lrelu(l.x + r.x), z1 = lrelu(l.y + r.y);
    float z2 = lrelu(l.z + r.z), z3 = lrelu(l.w + r.w);
    atten[eid] = 0.25f * (z0 + z1 + z2 + z3);
    if (LAYER == 1)
        *(float4*)(e1 + (size_t)eid * 4) = make_float4(z0, z1, z2, z3);
    *(float4*)(g_w + (size_t)i * 4) =
        make_float4(__expf(z0), __expf(z1), __expf(z2), __expf(z3));
}

// ---------------- warp-per-node: coalesced denom + weighted gather -------
template <int LAYER>
__global__ __launch_bounds__(256) void node_agg_kernel(const float* __restrict__ feat,
                                                       float* __restrict__ out) {
    int node = blockIdx.x * 8 + (threadIdx.x >> 5);
    if (node >= NN) return;
    int lane = threadIdx.x & 31;
    int beg = g_rowptr[node], end = g_rowptr[node + 1];

    // pass 1: coalesced per-head denom
    float4 s = make_float4(0.f, 0.f, 0.f, 0.f);
    for (int i = beg + lane; i < end; i += 32) {
        float4 wv = *(const float4*)(g_w + (size_t)i * 4);
        s.x += wv.x; s.y += wv.y; s.z += wv.z; s.w += wv.w;
    }
#pragma unroll
    for (int o = 16; o; o >>= 1) {
        s.x += __shfl_xor_sync(0xffffffffu, s.x, o);
        s.y += __shfl_xor_sync(0xffffffffu, s.y, o);
        s.z += __shfl_xor_sync(0xffffffffu, s.z, o);
        s.w += __shfl_xor_sync(0xffffffffu, s.w, o);
    }

    int h = lane >> 3;
    float dh = (h == 0) ? s.x : (h == 1) ? s.y : (h == 2) ? s.z : s.w;
    float inv = dh > 0.f ? 1.f / dh : 0.f;

    // pass 2: weighted gather-accumulate, 2 edges in flight
    float4 acc = make_float4(0.f, 0.f, 0.f, 0.f);
    int i = beg;
    for (; i + 2 <= end; i += 2) {
        int s0 = g_csr_src[i], s1 = g_csr_src[i + 1];
        float a0 = __ldg(g_w + (size_t)i * 4 + h) * inv;
        float a1 = __ldg(g_w + (size_t)(i + 1) * 4 + h) * inv;
        float4 f0 = *(const float4*)(feat + (size_t)s0 * HD + lane * 4);
        float4 f1 = *(const float4*)(feat + (size_t)s1 * HD + lane * 4);
        acc.x += f0.x * a0 + f1.x * a1;
        acc.y += f0.y * a0 + f1.y * a1;
        acc.z += f0.z * a0 + f1.z * a1;
        acc.w += f0.w * a0 + f1.w * a1;
    }
    if (i < end) {
        int s0 = g_csr_src[i];
        float a0 = __ldg(g_w + (size_t)i * 4 + h) * inv;
        float4 f0 = *(const float4*)(feat + (size_t)s0 * HD + lane * 4);
        acc.x += f0.x * a0; acc.y += f0.y * a0;
        acc.z += f0.z * a0; acc.w += f0.w * a0;
    }

    if (LAYER == 0) {
        acc.x = elu1(acc.x); acc.y = elu1(acc.y);
        acc.z = elu1(acc.z); acc.w = elu1(acc.w);
        *(float4*)(out + (size_t)node * HD + lane * 4) = acc;  // out = g_h1
    } else {
        float4 r = *(const float4*)(g_h1 + (size_t)node * HD + lane * 4);
        acc.x = elu1(acc.x + r.x); acc.y = elu1(acc.y + r.y);
        acc.z = elu1(acc.z + r.z); acc.w = elu1(acc.w + r.w);
        *(float4*)(out + (size_t)node * HD + lane * 4) = acc;  // temp [N,128]
        int d = (lane * 4) & 31;
        float* headp = out + (size_t)NN * HD + (size_t)h * NN * D + (size_t)node * D + d;
        *(float4*)headp = acc;
    }
}

static inline int cdiv(int a, int b) { return (a + b - 1) / b; }

extern "C" void kernel_launch(void* const* d_in, const int* in_sizes, int n_in,
                              void* d_out, int out_size) {
    const float* x   = (const float*)d_in[0];
    const int*   ei  = (const int*)d_in[1];
    const float* W0  = (const float*)d_in[2];
    const float* al0 = (const float*)d_in[3];
    const float* ar0 = (const float*)d_in[4];
    const float* W1  = (const float*)d_in[5];
    const float* al1 = (const float*)d_in[6];
    const float* ar1 = (const float*)d_in[7];
    float* out = (float*)d_out;

    float* e1_out = out + (size_t)NN * HD + (size_t)H * NN * D;  // [E, H]
    float* atten0 = e1_out + (size_t)EE * H;                     // [E]
    float* atten1 = atten0 + EE;                                 // [E]

    void *p_feat, *p_h1;
    cudaGetSymbolAddress(&p_feat, g_feat);
    cudaGetSymbolAddress(&p_h1, g_h1);
    float* feat = (float*)p_feat;
    float* h1   = (float*)p_h1;

    const int T = 256;
    int g_gemm = cdiv(NN, 64);
    int g_edge = cdiv(EE, T);
    int g_node = cdiv(NN, 8);

    cudaStream_t side;
    cudaStreamCreateWithFlags(&side, cudaStreamNonBlocking);
    cudaEvent_t evFork0, evJoin0;
    cudaEventCreateWithFlags(&evFork0, cudaEventDisableTiming);
    cudaEventCreateWithFlags(&evJoin0, cudaEventDisableTiming);

    // ---- fork: CSR build on side stream, concurrent with layer-0 GEMM ----
    cudaEventRecord(evFork0, 0);
    cudaStreamWaitEvent(side, evFork0, 0);
    count_deg_kernel<<<g_edge, T, 0, side>>>(ei);                // 1
    scan1_kernel<<<NBLK1, SCAN_BS, 0, side>>>();                 // 2
    scan2_kernel<<<1, 256, 0, side>>>();                         // 3
    sgemm_tf32<<<g_gemm, T>>>(x, W0, al0, ar0, feat, NN, IN_DIM);// 4 <- profiled
    scan3_kernel<<<NBLK1, SCAN_BS, 0, side>>>();                 // 5
    fill_csr_kernel<<<g_edge, T, 0, side>>>(ei);                 // 6
    cudaEventRecord(evJoin0, side);

    // ---- join: edge_w needs CSR + GEMM0 ----
    cudaStreamWaitEvent(0, evJoin0, 0);
    edge_w_kernel<0><<<g_edge, T>>>(atten0, nullptr);            // 7
    node_agg_kernel<0><<<g_node, T>>>(feat, h1);                 // 8

    // ---- layer 1 ----
    sgemm_tf32<<<g_gemm, T>>>(h1, W1, al1, ar1, feat, NN, HD);   // 9
    edge_w_kernel<1><<<g_edge, T>>>(atten1, e1_out);             // 10
    node_agg_kernel<1><<<g_node, T>>>(feat, out);                // 11
}